// round 1
// baseline (speedup 1.0000x reference)
#include <cuda_runtime.h>

#define BB 2
#define NF 16
#define HH 512
#define WW 512
#define H2 1024
#define W2 1024
#define CINc 50
#define HW (HH*WW)
#define HW2 (H2*W2)

// -------- scratch (device globals; no allocations allowed) --------
__device__ float g_up16 [(size_t)BB*NF*HW2];   // upsampled tgt, planar [B][16][1024][1024]
__device__ float g_w1024[(size_t)BB*NF*HW2];   // warped tgt @1024, planar
__device__ float g_warped[(size_t)BB*NF*HW];   // warped tgt @512, planar
__device__ float g_adj  [(size_t)BB*2*HW];     // conv output, planar [B][2][512][512]
__device__ float g_newres[(size_t)BB*2*HW];    // combined residual, planar
__device__ float g_a1024 [(size_t)BB*HW2*2];   // upsampled res *2, interleaved (x,y)
__device__ float g_b1024 [(size_t)BB*HW2*2];   // upsampled adj *2
__device__ float g_nr1024[(size_t)BB*HW2*2];   // upsampled new_res *2
__device__ float g_wr1024[(size_t)BB*HW2*2];   // warped res field @1024

// -------- resize helpers (match jax.image.resize bilinear, antialias) --------
__device__ __forceinline__ void up_taps(int i, int n_in, int& t0, int& t1,
                                        float& w0, float& w1) {
    int k = i >> 1;
    if ((i & 1) == 0) { t0 = k - 1; t1 = k;     w0 = 0.25f; w1 = 0.75f; }
    else              { t0 = k;     t1 = k + 1; w0 = 0.75f; w1 = 0.25f; }
    if (t0 < 0)     { t0 = t1; w0 = 0.f; w1 = 1.f; }   // edge renorm (0.75/0.75)
    if (t1 >= n_in) { t1 = t0; w1 = 0.f; w0 = 1.f; }
}
__device__ __forceinline__ float dbase(int t) { return (t == 0 || t == 3) ? 0.25f : 0.75f; }

// -------- kernel 1: upsample tgt 512->1024, planar --------
__global__ void k_up_img(const float* __restrict__ x) {
    int idx = blockIdx.x * blockDim.x + threadIdx.x;
    if (idx >= BB * HW2) return;
    int xx = idx & (W2 - 1), yy = (idx >> 10) & (H2 - 1), b = idx >> 20;
    int ty0, ty1, tx0, tx1; float wy0, wy1, wx0, wx1;
    up_taps(yy, HH, ty0, ty1, wy0, wy1);
    up_taps(xx, WW, tx0, tx1, wx0, wx1);
    int r0 = ty0 * WW, r1 = ty1 * WW;
    const float* xb = x + ((size_t)b * 2 * NF + NF) * HW;   // tgt channels 16..31
    float* ob = g_up16 + (size_t)b * NF * HW2 + yy * W2 + xx;
    #pragma unroll
    for (int c = 0; c < NF; c++) {
        const float* p = xb + (size_t)c * HW;
        float v = wy0 * (wx0 * p[r0 + tx0] + wx1 * p[r0 + tx1])
                + wy1 * (wx0 * p[r1 + tx0] + wx1 * p[r1 + tx1]);
        ob[(size_t)c * HW2] = v;
    }
}

// -------- kernel 2: upsample a 2-channel residual field 512->1024, *scale --------
// src_sel: 0 = external (res input), 1 = g_adj, 2 = g_newres
// dst_sel: 0 = g_a1024, 1 = g_b1024, 2 = g_nr1024
__global__ void k_up_res(const float* __restrict__ src_ext, int src_sel, int dst_sel,
                         float scale) {
    int idx = blockIdx.x * blockDim.x + threadIdx.x;
    if (idx >= BB * HW2) return;
    int xx = idx & (W2 - 1), yy = (idx >> 10) & (H2 - 1), b = idx >> 20;
    const float* src = (src_sel == 0) ? src_ext : ((src_sel == 1) ? g_adj : g_newres);
    int ty0, ty1, tx0, tx1; float wy0, wy1, wx0, wx1;
    up_taps(yy, HH, ty0, ty1, wy0, wy1);
    up_taps(xx, WW, tx0, tx1, wx0, wx1);
    int r0 = ty0 * WW, r1 = ty1 * WW;
    const float* p0 = src + (size_t)b * 2 * HW;
    const float* p1 = p0 + HW;
    float vx = wy0 * (wx0 * p0[r0 + tx0] + wx1 * p0[r0 + tx1])
             + wy1 * (wx0 * p0[r1 + tx0] + wx1 * p0[r1 + tx1]);
    float vy = wy0 * (wx0 * p1[r0 + tx0] + wx1 * p1[r0 + tx1])
             + wy1 * (wx0 * p1[r1 + tx0] + wx1 * p1[r1 + tx1]);
    float2* dst = (float2*)((dst_sel == 0) ? g_a1024 : ((dst_sel == 1) ? g_b1024 : g_nr1024));
    dst[idx] = make_float2(vx * scale, vy * scale);
}

// -------- corner weight/offset computation for zero-padded bilinear gather --------
__device__ __forceinline__ void gather_setup(float sx, float sy,
        int& o00, int& o01, int& o10, int& o11,
        float& w00, float& w01, float& w10, float& w11) {
    float xf = floorf(sx), yf = floorf(sy);
    float fx = sx - xf, fy = sy - yf;
    int ix0 = (int)xf, iy0 = (int)yf;
    int ix1 = ix0 + 1, iy1 = iy0 + 1;
    w00 = (1.f - fy) * (1.f - fx); w01 = (1.f - fy) * fx;
    w10 = fy * (1.f - fx);         w11 = fy * fx;
    bool bx0 = (unsigned)ix0 < W2, bx1 = (unsigned)ix1 < W2;
    bool by0 = (unsigned)iy0 < H2, by1 = (unsigned)iy1 < H2;
    if (!(by0 && bx0)) w00 = 0.f;
    if (!(by0 && bx1)) w01 = 0.f;
    if (!(by1 && bx0)) w10 = 0.f;
    if (!(by1 && bx1)) w11 = 0.f;
    int cx0 = min(max(ix0, 0), W2 - 1), cx1 = min(max(ix1, 0), W2 - 1);
    int cy0 = min(max(iy0, 0), H2 - 1), cy1 = min(max(iy1, 0), H2 - 1);
    o00 = cy0 * W2 + cx0; o01 = cy0 * W2 + cx1;
    o10 = cy1 * W2 + cx0; o11 = cy1 * W2 + cx1;
}

// -------- kernel 3: warp 16-channel image @1024 (field_sel: 0=a1024, 1=nr1024) --------
__global__ void k_warp_img(int field_sel) {
    int idx = blockIdx.x * blockDim.x + threadIdx.x;
    if (idx >= BB * HW2) return;
    int xx = idx & (W2 - 1), yy = (idx >> 10) & (H2 - 1), b = idx >> 20;
    const float2* fld = (const float2*)((field_sel == 0) ? g_a1024 : g_nr1024);
    float2 f = fld[idx];
    int o00, o01, o10, o11; float w00, w01, w10, w11;
    gather_setup((float)xx + f.x, (float)yy + f.y, o00, o01, o10, o11, w00, w01, w10, w11);
    const float* img = g_up16 + (size_t)b * NF * HW2;
    float* out = g_w1024 + (size_t)b * NF * HW2 + yy * W2 + xx;
    #pragma unroll
    for (int c = 0; c < NF; c++) {
        const float* p = img + (size_t)c * HW2;
        out[(size_t)c * HW2] = w00 * p[o00] + w01 * p[o01] + w10 * p[o10] + w11 * p[o11];
    }
}

// -------- kernel 4: downsample 16-channel image 1024->512 --------
// to_final=0 -> g_warped; to_final=1 -> final_out channels 16..31 of 32
__global__ void k_down_img(float* __restrict__ final_out, int to_final) {
    int idx = blockIdx.x * blockDim.x + threadIdx.x;
    if (idx >= BB * HW) return;
    int xx = idx & (WW - 1), yy = (idx >> 9) & (HH - 1), b = idx >> 18;
    float invsy = (yy == 0 || yy == HH - 1) ? (1.f / 1.75f) : 0.5f;
    float invsx = (xx == 0 || xx == WW - 1) ? (1.f / 1.75f) : 0.5f;
    float acc[NF];
    #pragma unroll
    for (int c = 0; c < NF; c++) acc[c] = 0.f;
    const float* img = g_w1024 + (size_t)b * NF * HW2;
    for (int ty = 0; ty < 4; ty++) {
        int Y = 2 * yy - 1 + ty;
        if ((unsigned)Y >= H2) continue;
        float wy = dbase(ty) * invsy;
        for (int tx = 0; tx < 4; tx++) {
            int X = 2 * xx - 1 + tx;
            if ((unsigned)X >= W2) continue;
            float w = wy * dbase(tx) * invsx;
            const float* p = img + Y * W2 + X;
            #pragma unroll
            for (int c = 0; c < NF; c++) acc[c] += w * p[(size_t)c * HW2];
        }
    }
    if (to_final) {
        float* o = final_out + ((size_t)b * 2 * NF + NF) * HW + yy * WW + xx;
        #pragma unroll
        for (int c = 0; c < NF; c++) o[(size_t)c * HW] = acc[c];
    } else {
        float* o = g_warped + (size_t)b * NF * HW + yy * WW + xx;
        #pragma unroll
        for (int c = 0; c < NF; c++) o[(size_t)c * HW] = acc[c];
    }
}

// -------- kernel 5: 3x3 conv, 50 -> 2 channels --------
__global__ void k_conv(const float* __restrict__ x, const float* __restrict__ res,
                       const float* __restrict__ Wc, const float* __restrict__ bias) {
    __shared__ float sw[2 * CINc * 9];
    for (int i = threadIdx.x; i < 2 * CINc * 9; i += blockDim.x) sw[i] = Wc[i];
    __syncthreads();
    int idx = blockIdx.x * blockDim.x + threadIdx.x;
    if (idx >= BB * HW) return;
    int xx = idx & (WW - 1), yy = (idx >> 9) & (HH - 1), b = idx >> 18;
    float a0 = bias[0], a1 = bias[1];
    const float* xb = x + (size_t)b * 2 * NF * HW;
    const float* wb = g_warped + (size_t)b * NF * HW;
    const float* rb = res + (size_t)b * 2 * HW;
    for (int dy = -1; dy <= 1; dy++) {
        int y2 = yy + dy;
        if ((unsigned)y2 >= HH) continue;
        for (int dx = -1; dx <= 1; dx++) {
            int x2 = xx + dx;
            if ((unsigned)x2 >= WW) continue;
            int kidx = (dy + 1) * 3 + (dx + 1);
            int p = y2 * WW + x2;
            const float* s0 = sw + kidx;
            const float* s1 = sw + CINc * 9 + kidx;
            #pragma unroll 8
            for (int c = 0; c < 32; c++) {        // src + tgt straight from x
                float v = xb[(size_t)c * HW + p];
                a0 += v * s0[c * 9];
                a1 += v * s1[c * 9];
            }
            #pragma unroll 8
            for (int c = 0; c < 16; c++) {        // warped tgt
                float v = wb[(size_t)c * HW + p];
                a0 += v * s0[(32 + c) * 9];
                a1 += v * s1[(32 + c) * 9];
            }
            float v0 = rb[p], v1 = rb[HW + p];    // residual channels
            a0 += v0 * s0[48 * 9] + v1 * s0[49 * 9];
            a1 += v0 * s1[48 * 9] + v1 * s1[49 * 9];
        }
    }
    float* o = g_adj + (size_t)b * 2 * HW + yy * WW + xx;
    o[0] = a0;
    o[HW] = a1;
}

// -------- kernel 6: warp 2-channel residual field a1024 by b1024 --------
__global__ void k_warp_res() {
    int idx = blockIdx.x * blockDim.x + threadIdx.x;
    if (idx >= BB * HW2) return;
    int xx = idx & (W2 - 1), yy = (idx >> 10) & (H2 - 1), b = idx >> 20;
    float2 f = ((const float2*)g_b1024)[idx];
    int o00, o01, o10, o11; float w00, w01, w10, w11;
    gather_setup((float)xx + f.x, (float)yy + f.y, o00, o01, o10, o11, w00, w01, w10, w11);
    const float2* a = (const float2*)g_a1024 + (size_t)b * HW2;
    float2 v00 = a[o00], v01 = a[o01], v10 = a[o10], v11 = a[o11];
    float ax = w00 * v00.x + w01 * v01.x + w10 * v10.x + w11 * v11.x;
    float ay = w00 * v00.y + w01 * v01.y + w10 * v10.y + w11 * v11.y;
    ((float2*)g_wr1024)[idx] = make_float2(ax, ay);
}

// -------- kernel 7: downsample warped residual (x0.5) + add adj -> new_res --------
__global__ void k_combine() {
    int idx = blockIdx.x * blockDim.x + threadIdx.x;
    if (idx >= BB * HW) return;
    int xx = idx & (WW - 1), yy = (idx >> 9) & (HH - 1), b = idx >> 18;
    float invsy = (yy == 0 || yy == HH - 1) ? (1.f / 1.75f) : 0.5f;
    float invsx = (xx == 0 || xx == WW - 1) ? (1.f / 1.75f) : 0.5f;
    float ax = 0.f, ay = 0.f;
    const float2* w1 = (const float2*)g_wr1024 + (size_t)b * HW2;
    for (int ty = 0; ty < 4; ty++) {
        int Y = 2 * yy - 1 + ty;
        if ((unsigned)Y >= H2) continue;
        float wy = dbase(ty) * invsy;
        for (int tx = 0; tx < 4; tx++) {
            int X = 2 * xx - 1 + tx;
            if ((unsigned)X >= W2) continue;
            float w = wy * dbase(tx) * invsx;
            float2 v = w1[Y * W2 + X];
            ax += w * v.x;
            ay += w * v.y;
        }
    }
    const float* ad = g_adj + (size_t)b * 2 * HW;
    float* nr = g_newres + (size_t)b * 2 * HW;
    int p = yy * WW + xx;
    nr[p]      = ad[p]      + 0.5f * ax;   // _resize_res down: resize * (1/f)
    nr[HW + p] = ad[HW + p] + 0.5f * ay;
}

// -------- launch --------
extern "C" void kernel_launch(void* const* d_in, const int* in_sizes, int n_in,
                              void* d_out, int out_size) {
    const float* x    = (const float*)d_in[0];
    const float* res  = (const float*)d_in[1];
    const float* Wc   = (const float*)d_in[2];
    const float* bias = (const float*)d_in[3];
    float* out = (float*)d_out;

    const int T = 256;
    const int n1024 = BB * HW2;   // 2,097,152
    const int n512  = BB * HW;    //   524,288
    dim3 g1((n1024 + T - 1) / T), g2((n512 + T - 1) / T);

    // src channels pass through untouched: out[b][0..15] = x[b][0..15]
    for (int b = 0; b < BB; b++) {
        cudaMemcpyAsync(out + (size_t)b * 2 * NF * HW,
                        x   + (size_t)b * 2 * NF * HW,
                        sizeof(float) * (size_t)NF * HW,
                        cudaMemcpyDeviceToDevice, 0);
    }

    k_up_img<<<g1, T>>>(x);                           // tgt -> g_up16 (reused by both warps)
    k_up_res<<<g1, T>>>(res, 0, 0, 2.f);              // res -> g_a1024 (*2)
    k_warp_img<<<g1, T>>>(0);                         // warp tgt by a1024 -> g_w1024
    k_down_img<<<g2, T>>>(nullptr, 0);                // -> g_warped (512)
    k_conv<<<g2, T>>>(x, res, Wc, bias);              // bundle conv -> g_adj
    k_up_res<<<g1, T>>>(nullptr, 1, 1, 2.f);          // adj -> g_b1024 (*2)
    k_warp_res<<<g1, T>>>();                          // warp a1024 by b1024 -> g_wr1024
    k_combine<<<g2, T>>>();                           // new_res = adj + 0.5*down(wr1024)
    k_up_res<<<g1, T>>>(nullptr, 2, 2, 2.f);          // new_res -> g_nr1024 (*2)
    k_warp_img<<<g1, T>>>(1);                         // warp tgt by nr1024 -> g_w1024
    k_down_img<<<g2, T>>>(out, 1);                    // -> out channels 16..31
}